// round 2
// baseline (speedup 1.0000x reference)
#include <cuda_runtime.h>
#include <cstdint>

// ---------------------------------------------------------------------------
// Problem shapes (fixed by the dataset)
// ---------------------------------------------------------------------------
#define B 8
#define C 64
#define H 128
#define W 128
#define HW (H * W)            // 16384
#define BHW (B * HW)          // 131072
#define NEVAL 17              // mid + 4 noise dirs * 4 coeffs

// Output layout: [convex_loss(1), mid(1), tfm(BHW), ifm(BHW)]
#define OUT_TFM_OFF 2
#define OUT_IFM_OFF (2 + BHW)

struct LamParams {
    float lam[4][9];
};

// Deterministic scratch: per-(eval, block) partial sums, then per-eval sums.
// 17 evals x (8 batches * 64 pixel-blocks) = 17 x 512
__device__ double g_part[NEVAL][512];
__device__ double g_sums[NEVAL];

// ---------------------------------------------------------------------------
// Kernel 1: calc_fmap  (structure-tensor mimic ratio), smem-tiled
// ---------------------------------------------------------------------------
#define TSX 32
#define TSY 8

__global__ __launch_bounds__(TSX * TSY)
void fmap_kernel(const float* __restrict__ x, float* __restrict__ out)
{
    __shared__ float tile[TSY + 2][TSX + 2];

    const int b  = blockIdx.z;
    const int x0 = blockIdx.x * TSX;
    const int y0 = blockIdx.y * TSY;
    const int lx = threadIdx.x;
    const int ly = threadIdx.y;
    const int tid = ly * TSX + lx;

    const float* xb = x + (size_t)b * C * HW;

    float A[9];
    float S1[9];
    float T2 = 0.f;
#pragma unroll
    for (int k = 0; k < 9; k++) { A[k] = 0.f; S1[k] = 0.f; }

    for (int c = 0; c < C; c++) {
        const float* xc = xb + c * HW;
        // cooperative load of (TSY+2) x (TSX+2) = 340 floats (zero pad outside)
        for (int i = tid; i < (TSY + 2) * (TSX + 2); i += TSX * TSY) {
            int ry = i / (TSX + 2);
            int rx = i - ry * (TSX + 2);
            int gy = y0 + ry - 1;
            int gx = x0 + rx - 1;
            float v = 0.f;
            if (gy >= 0 && gy < H && gx >= 0 && gx < W)
                v = __ldg(&xc[gy * W + gx]);
            tile[ry][rx] = v;
        }
        __syncthreads();

        float v[9];
#pragma unroll
        for (int dy = 0; dy < 3; dy++)
#pragma unroll
            for (int dx = 0; dx < 3; dx++)
                v[dy * 3 + dx] = tile[ly + dy][lx + dx];

        float s = 0.f;
#pragma unroll
        for (int k = 0; k < 9; k++) s += v[k];
#pragma unroll
        for (int k = 0; k < 9; k++) {
            A[k]  = fmaf(v[k], s, A[k]);
            S1[k] += v[k];
            T2    = fmaf(v[k], v[k], T2);
        }
        __syncthreads();
    }

    // finalize
    float mu[9];
    float M = 0.f, musq = 0.f;
#pragma unroll
    for (int k = 0; k < 9; k++) {
        mu[k] = S1[k] * (1.f / C);
        M    += mu[k];
        musq  = fmaf(mu[k], mu[k], musq);
    }
    float trace = T2 - (float)C * musq;

    float rmax = -3.4e38f, rmin = 3.4e38f;
#pragma unroll
    for (int k = 0; k < 9; k++) {
        float rs = A[k] - (float)C * mu[k] * M;
        rmax = fmaxf(rmax, rs);
        rmin = fminf(rmin, rs);
    }
    float ratio = (rmax + rmin) * 0.5f / trace;

    out[(size_t)b * HW + (y0 + ly) * W + (x0 + lx)] = ratio;
}

// ---------------------------------------------------------------------------
// Kernel 2: warp + ssim accumulation for all 17 homography evaluations
//   grid: (64 pixel blocks, 8 batches, 17 evals), block 256
// ---------------------------------------------------------------------------
__global__ __launch_bounds__(256)
void ssim_kernel(const float* __restrict__ tfm, const float* __restrict__ ifm,
                 const float* __restrict__ tw,  const float* __restrict__ iw,
                 const float* __restrict__ Hgt, LamParams P)
{
    const int e   = blockIdx.z;         // eval 0..16
    const int b   = blockIdx.y;         // batch
    const int idx = blockIdx.x * 256 + threadIdx.x;  // pixel 0..16383

    // eval -> (n, coeff)
    float cf = 0.f;
    int n = 0;
    if (e > 0) {
        n = (e - 1) >> 2;
        int j = (e - 1) & 3;
        const float cs[4] = {1.f, 2.f, -1.f, -2.f};
        cf = cs[j];
    }

    float Hm[9];
#pragma unroll
    for (int i = 0; i < 9; i++) {
        float h = __ldg(&Hgt[b * 9 + i]);
        Hm[i] = h * (1.f + cf * P.lam[n][i]);
    }

    const int y = idx >> 7;
    const int x = idx & 127;
    const float fx = (float)x, fy = (float)y;

    float Z  = fmaf(Hm[6], fx, fmaf(Hm[7], fy, Hm[8]));
    float Xp = fmaf(Hm[0], fx, fmaf(Hm[1], fy, Hm[2]));
    float Yp = fmaf(Hm[3], fx, fmaf(Hm[4], fy, Hm[5]));
    float px = Xp / Z;
    float py = Yp / Z;

    float x0f = floorf(px), y0f = floorf(py);
    float x1f = x0f + 1.f,  y1f = y0f + 1.f;
    float wa = (x1f - px) * (y1f - py);
    float wb = (x1f - px) * (py - y0f);
    float wc = (px - x0f) * (y1f - py);
    float wd = (px - x0f) * (py - y0f);

    const float* fb  = ifm + (size_t)b * HW;
    const float* wbp = iw  + (size_t)b * HW;

    float wfm = 0.f, ww = 0.f;

    // four taps matching the reference's validity semantics
#pragma unroll
    for (int t = 0; t < 4; t++) {
        float xi = (t & 2) ? x1f : x0f;
        float yi = (t & 1) ? y1f : y0f;
        float wt = (t == 0) ? wa : (t == 1) ? wb : (t == 2) ? wc : wd;
        float valid = (xi >= 0.f && xi <= (float)(W - 1) &&
                       yi >= 0.f && yi <= (float)(H - 1)) ? 1.f : 0.f;
        int xc = (int)fminf(fmaxf(xi, 0.f), (float)(W - 1));
        int yc = (int)fminf(fmaxf(yi, 0.f), (float)(H - 1));
        int off = yc * W + xc;
        wfm = fmaf(wt, __ldg(&fb[off])  * valid, wfm);
        ww  = fmaf(wt, __ldg(&wbp[off]) * valid, ww);
    }

    float t0 = __ldg(&tfm[(size_t)b * HW + idx]);
    float tw0 = __ldg(&tw[(size_t)b * HW + idx]);
    float d = t0 - wfm;
    double term = (double)(tw0 * ww) * (double)(d * d);

    // block reduction (deterministic within block; partials combined in fixed
    // order by reduce_kernel -> fully deterministic output)
    const int lane = threadIdx.x & 31;
    const int warp = threadIdx.x >> 5;
#pragma unroll
    for (int o = 16; o > 0; o >>= 1)
        term += __shfl_down_sync(0xffffffffu, term, o);
    __shared__ double wsum[8];
    if (lane == 0) wsum[warp] = term;
    __syncthreads();
    if (warp == 0) {
        double s = (lane < 8) ? wsum[lane] : 0.0;
#pragma unroll
        for (int o = 4; o > 0; o >>= 1)
            s += __shfl_down_sync(0xffffffffu, s, o);
        if (lane == 0)
            g_part[e][b * 64 + blockIdx.x] = s;
    }
}

// ---------------------------------------------------------------------------
// Kernel 3: deterministic per-eval reduction  (grid = 17, block = 256)
// ---------------------------------------------------------------------------
__global__ __launch_bounds__(256)
void reduce_kernel()
{
    const int e = blockIdx.x;
    const int t = threadIdx.x;
    double s = g_part[e][t] + g_part[e][t + 256];
    const int lane = t & 31, warp = t >> 5;
#pragma unroll
    for (int o = 16; o > 0; o >>= 1)
        s += __shfl_down_sync(0xffffffffu, s, o);
    __shared__ double wsum[8];
    if (lane == 0) wsum[warp] = s;
    __syncthreads();
    if (warp == 0) {
        double v = (lane < 8) ? wsum[lane] : 0.0;
#pragma unroll
        for (int o = 4; o > 0; o >>= 1)
            v += __shfl_down_sync(0xffffffffu, v, o);
        if (lane == 0) g_sums[e] = v;
    }
}

// ---------------------------------------------------------------------------
// Kernel 4: combine into convex_loss + mid
// ---------------------------------------------------------------------------
__global__ void combine_kernel(float* __restrict__ out, LamParams P)
{
    const double inv = 1.0 / (double)BHW;
    double mid = g_sums[0] * inv;
    double loss = 0.0;
#pragma unroll
    for (int n = 0; n < 4; n++) {
        double sL  = g_sums[1 + 4 * n] * inv;
        double sLL = g_sums[2 + 4 * n] * inv;
        double sR  = g_sums[3 + 4 * n] * inv;
        double sRR = g_sums[4 + 4 * n] * inv;
        float s2f = 0.f;
#pragma unroll
        for (int i = 0; i < 9; i++) s2f = fmaf(P.lam[n][i], P.lam[n][i], s2f);
        double s2 = (double)s2f;
        double d2 = 3.0 * s2;   // sum((2l)^2) - sum(l^2)
        loss -= fmin(sL - mid - s2, 0.0);
        loss -= fmin(sL - sLL + d2, 0.0);
        loss -= fmin(sR - mid - s2, 0.0);
        loss -= fmin(sR - sRR + d2, 0.0);
    }
    out[0] = (float)loss;
    out[1] = (float)mid;
}

// ---------------------------------------------------------------------------
// Host: JAX Threefry-2x32 replication for gen_lambda.
// JAX >= 0.4.36 default: jax_threefry_partitionable=True, so random_bits for
// 32-bit draws at flat index i is:
//     (o0, o1) = threefry2x32(key, hi32(i), lo32(i));  bits = o0 ^ o1
// fold_in is unchanged: new_key = threefry2x32(key, [0, n]).
// ---------------------------------------------------------------------------
static inline void threefry2x32(uint32_t k0, uint32_t k1,
                                uint32_t x0, uint32_t x1,
                                uint32_t* o0, uint32_t* o1)
{
    const uint32_t ks[3] = {k0, k1, k0 ^ k1 ^ 0x1BD11BDAu};
    uint32_t v0 = x0 + ks[0];
    uint32_t v1 = x1 + ks[1];
    static const int rot[2][4] = {{13, 15, 26, 6}, {17, 29, 16, 24}};
    for (int g = 0; g < 5; g++) {
        const int* r = rot[g & 1];
        for (int i = 0; i < 4; i++) {
            v0 += v1;
            v1 = (v1 << r[i]) | (v1 >> (32 - r[i]));
            v1 ^= v0;
        }
        v0 += ks[(g + 1) % 3];
        v1 += ks[(g + 2) % 3] + (uint32_t)(g + 1);
    }
    *o0 = v0;
    *o1 = v1;
}

static void compute_lambdas(LamParams* P)
{
    for (int n = 0; n < 4; n++) {
        // fold_in(key(42), n): encrypt count [0, n] with key (0, 42)
        uint32_t k0, k1;
        threefry2x32(0u, 42u, 0u, (uint32_t)n, &k0, &k1);

        // partitionable random_bits, shape (9,), 32-bit:
        // per element i: bits = o0 ^ o1 of threefry2x32(key, 0, i)
        for (int i = 0; i < 9; i++) {
            uint32_t o0, o1;
            threefry2x32(k0, k1, 0u, (uint32_t)i, &o0, &o1);
            uint32_t bits = o0 ^ o1;

            uint32_t fb = (bits >> 9) | 0x3f800000u;
            float u;
            __builtin_memcpy(&u, &fb, 4);
            u -= 1.0f;                       // uniform [0,1)
            float lam = (u - 0.5f) / 6.0f;
            if (lam > 0.f && lam < 0.02f)  lam = 0.02f;
            if (lam < 0.f && lam > -0.02f) lam = -0.02f;
            P->lam[n][i] = lam;
        }
        P->lam[n][8] = 0.0f;
    }
}

// ---------------------------------------------------------------------------
// Entry point
// ---------------------------------------------------------------------------
extern "C" void kernel_launch(void* const* d_in, const int* in_sizes, int n_in,
                              void* d_out, int out_size)
{
    (void)in_sizes; (void)n_in; (void)out_size;
    const float* tfeat = (const float*)d_in[0];
    const float* ifeat = (const float*)d_in[1];
    const float* tw    = (const float*)d_in[2];
    const float* iw    = (const float*)d_in[3];
    const float* Hgt   = (const float*)d_in[4];
    float* out = (float*)d_out;

    LamParams P;
    compute_lambdas(&P);

    float* tfm = out + OUT_TFM_OFF;
    float* ifm = out + OUT_IFM_OFF;

    dim3 fblk(TSX, TSY);
    dim3 fgrd(W / TSX, H / TSY, B);
    fmap_kernel<<<fgrd, fblk>>>(tfeat, tfm);
    fmap_kernel<<<fgrd, fblk>>>(ifeat, ifm);

    dim3 sgrd(HW / 256, B, NEVAL);
    ssim_kernel<<<sgrd, 256>>>(tfm, ifm, tw, iw, Hgt, P);

    reduce_kernel<<<NEVAL, 256>>>();
    combine_kernel<<<1, 1>>>(out, P);
}

// round 3
// speedup vs baseline: 1.2553x; 1.2553x over previous
#include <cuda_runtime.h>
#include <cstdint>

#define B 8
#define C 64
#define H 128
#define W 128
#define HW (H * W)            // 16384
#define BHW (B * HW)          // 131072
#define NEVAL 17

#define OUT_TFM_OFF 2
#define OUT_IFM_OFF (2 + BHW)

struct LamParams {
    float lam[4][9];
};

// per-(eval, batch*block) partials
__device__ double g_part[NEVAL][512];

// ---------------------------------------------------------------------------
// Kernel 1: calc_fmap for BOTH inputs (grid.z = 16: z<8 template, z>=8 input)
//   tile 32x16 pixels, 256 threads, 2 pixels (vertical pair) per thread,
//   double-buffered channel loop, P/Q channel-sum trick.
// ---------------------------------------------------------------------------
#define TSX 32
#define TSY 16
#define TPAD (TSX + 2)        // 34
#define TROWS (TSY + 2)       // 18
#define TELEM (TROWS * TPAD)  // 612

__global__ __launch_bounds__(256)
void fmap_kernel(const float* __restrict__ tfeat, const float* __restrict__ ifeat,
                 float* __restrict__ out)
{
    __shared__ float buf[2][TROWS][TPAD];
    __shared__ float Pt[TROWS][TPAD];
    __shared__ float Qt[TROWS][TPAD];

    const int z  = blockIdx.z;                 // 0..15
    const int b  = (z < B) ? z : (z - B);
    const float* xb = ((z < B) ? tfeat : ifeat) + (size_t)b * C * HW;
    float* ob = out + (size_t)z * HW;          // tfm then ifm, contiguous

    const int x0 = blockIdx.x * TSX;
    const int y0 = blockIdx.y * TSY;
    const int lx = threadIdx.x;
    const int ly = threadIdx.y;                // 0..7
    const int tid = ly * TSX + lx;

    // zero P/Q tiles
    for (int i = tid; i < TELEM; i += 256) {
        ((float*)Pt)[i] = 0.f;
        ((float*)Qt)[i] = 0.f;
    }

    float A0[9], A1[9];
#pragma unroll
    for (int k = 0; k < 9; k++) { A0[k] = 0.f; A1[k] = 0.f; }

    // prologue: load channel 0
    {
        const float* xc = xb;
        for (int i = tid; i < TELEM; i += 256) {
            int ry = i / TPAD;
            int rx = i - ry * TPAD;
            int gy = y0 + ry - 1;
            int gx = x0 + rx - 1;
            float v = 0.f;
            if ((unsigned)gy < (unsigned)H && (unsigned)gx < (unsigned)W)
                v = __ldg(&xc[gy * W + gx]);
            ((float*)buf[0])[i] = v;
            ((float*)Pt)[i] += v;
            ((float*)Qt)[i] = fmaf(v, v, ((float*)Qt)[i]);
        }
    }

    const int ry0 = 2 * ly;   // top tile-row for this thread's pixel pair

    for (int c = 0; c < C; c++) {
        __syncthreads();
        // prefetch next channel into the other buffer (also accumulates P/Q)
        if (c + 1 < C) {
            const float* xc = xb + (c + 1) * HW;
            float* dst = (float*)buf[(c + 1) & 1];
            for (int i = tid; i < TELEM; i += 256) {
                int ry = i / TPAD;
                int rx = i - ry * TPAD;
                int gy = y0 + ry - 1;
                int gx = x0 + rx - 1;
                float v = 0.f;
                if ((unsigned)gy < (unsigned)H && (unsigned)gx < (unsigned)W)
                    v = __ldg(&xc[gy * W + gx]);
                dst[i] = v;
                ((float*)Pt)[i] += v;
                ((float*)Qt)[i] = fmaf(v, v, ((float*)Qt)[i]);
            }
        }

        const float (*t)[TPAD] = buf[c & 1];
        float r[4][3];
#pragma unroll
        for (int j = 0; j < 4; j++)
#pragma unroll
            for (int d = 0; d < 3; d++)
                r[j][d] = t[ry0 + j][lx + d];

        float rs[4];
#pragma unroll
        for (int j = 0; j < 4; j++)
            rs[j] = r[j][0] + r[j][1] + r[j][2];
        float s0 = rs[0] + rs[1] + rs[2];
        float s1 = rs[1] + rs[2] + rs[3];

#pragma unroll
        for (int k = 0; k < 9; k++) {
            A0[k] = fmaf(r[k / 3][k % 3], s0, A0[k]);
            A1[k] = fmaf(r[1 + k / 3][k % 3], s1, A1[k]);
        }
    }
    __syncthreads();   // P/Q complete

    // finalize both pixels of this thread
#pragma unroll
    for (int j = 0; j < 2; j++) {
        const float* Ak = j ? A1 : A0;
        float S1[9], T2 = 0.f;
#pragma unroll
        for (int dy = 0; dy < 3; dy++)
#pragma unroll
            for (int dx = 0; dx < 3; dx++) {
                int k = dy * 3 + dx;
                S1[k] = Pt[ry0 + j + dy][lx + dx];
                T2 += Qt[ry0 + j + dy][lx + dx];
            }

        float mu[9], M = 0.f, musq = 0.f;
#pragma unroll
        for (int k = 0; k < 9; k++) {
            mu[k] = S1[k] * (1.f / C);
            M += mu[k];
            musq = fmaf(mu[k], mu[k], musq);
        }
        float trace = T2 - (float)C * musq;

        float rmax = -3.4e38f, rmin = 3.4e38f;
#pragma unroll
        for (int k = 0; k < 9; k++) {
            float rs2 = Ak[k] - (float)C * mu[k] * M;
            rmax = fmaxf(rmax, rs2);
            rmin = fminf(rmin, rs2);
        }
        float ratio = (rmax + rmin) * 0.5f / trace;
        ob[(y0 + ry0 + j) * W + (x0 + lx)] = ratio;
    }
}

// ---------------------------------------------------------------------------
// Kernel 2: warp + ssim, fp32 block reduction, all 17 evals
// ---------------------------------------------------------------------------
__global__ __launch_bounds__(256)
void ssim_kernel(const float* __restrict__ tfm, const float* __restrict__ ifm,
                 const float* __restrict__ tw,  const float* __restrict__ iw,
                 const float* __restrict__ Hgt, LamParams P)
{
    const int e   = blockIdx.z;
    const int b   = blockIdx.y;
    const int idx = blockIdx.x * 256 + threadIdx.x;

    float cf = 0.f;
    int n = 0;
    if (e > 0) {
        n = (e - 1) >> 2;
        int j = (e - 1) & 3;
        const float cs[4] = {1.f, 2.f, -1.f, -2.f};
        cf = cs[j];
    }

    float Hm[9];
#pragma unroll
    for (int i = 0; i < 9; i++) {
        float h = __ldg(&Hgt[b * 9 + i]);
        Hm[i] = h * (1.f + cf * P.lam[n][i]);
    }

    const int y = idx >> 7;
    const int x = idx & 127;
    const float fx = (float)x, fy = (float)y;

    float Z  = fmaf(Hm[6], fx, fmaf(Hm[7], fy, Hm[8]));
    float Xp = fmaf(Hm[0], fx, fmaf(Hm[1], fy, Hm[2]));
    float Yp = fmaf(Hm[3], fx, fmaf(Hm[4], fy, Hm[5]));
    float px = Xp / Z;
    float py = Yp / Z;

    float x0f = floorf(px), y0f = floorf(py);
    float x1f = x0f + 1.f,  y1f = y0f + 1.f;
    float wa = (x1f - px) * (y1f - py);
    float wb = (x1f - px) * (py - y0f);
    float wc = (px - x0f) * (y1f - py);
    float wd = (px - x0f) * (py - y0f);

    const float* fb  = ifm + (size_t)b * HW;
    const float* wbp = iw  + (size_t)b * HW;

    float wfm = 0.f, ww = 0.f;
#pragma unroll
    for (int t = 0; t < 4; t++) {
        float xi = (t & 2) ? x1f : x0f;
        float yi = (t & 1) ? y1f : y0f;
        float wt = (t == 0) ? wa : (t == 1) ? wb : (t == 2) ? wc : wd;
        float valid = (xi >= 0.f && xi <= (float)(W - 1) &&
                       yi >= 0.f && yi <= (float)(H - 1)) ? 1.f : 0.f;
        int xc = (int)fminf(fmaxf(xi, 0.f), (float)(W - 1));
        int yc = (int)fminf(fmaxf(yi, 0.f), (float)(H - 1));
        int off = yc * W + xc;
        wfm = fmaf(wt, __ldg(&fb[off])  * valid, wfm);
        ww  = fmaf(wt, __ldg(&wbp[off]) * valid, ww);
    }

    float t0  = __ldg(&tfm[(size_t)b * HW + idx]);
    float tw0 = __ldg(&tw[(size_t)b * HW + idx]);
    float d = t0 - wfm;
    float term = (tw0 * ww) * (d * d);

    const int lane = threadIdx.x & 31;
    const int warp = threadIdx.x >> 5;
#pragma unroll
    for (int o = 16; o > 0; o >>= 1)
        term += __shfl_down_sync(0xffffffffu, term, o);
    __shared__ float wsum[8];
    if (lane == 0) wsum[warp] = term;
    __syncthreads();
    if (warp == 0) {
        float s = (lane < 8) ? wsum[lane] : 0.f;
#pragma unroll
        for (int o = 4; o > 0; o >>= 1)
            s += __shfl_down_sync(0xffffffffu, s, o);
        if (lane == 0)
            g_part[e][b * 64 + blockIdx.x] = (double)s;
    }
}

// ---------------------------------------------------------------------------
// Kernel 3: final reduce + combine (single block, 512 threads)
// ---------------------------------------------------------------------------
__global__ __launch_bounds__(512)
void final_kernel(float* __restrict__ out, LamParams P)
{
    __shared__ double sums[NEVAL];
    __shared__ double wred[16];
    const int t = threadIdx.x;
    const int lane = t & 31, warp = t >> 5;

    for (int e = 0; e < NEVAL; e++) {
        double s = g_part[e][t];
#pragma unroll
        for (int o = 16; o > 0; o >>= 1)
            s += __shfl_down_sync(0xffffffffu, s, o);
        if (lane == 0) wred[warp] = s;
        __syncthreads();
        if (warp == 0) {
            double v = (lane < 16) ? wred[lane] : 0.0;
#pragma unroll
            for (int o = 8; o > 0; o >>= 1)
                v += __shfl_down_sync(0xffffffffu, v, o);
            if (lane == 0) sums[e] = v;
        }
        __syncthreads();
    }

    if (t == 0) {
        const double inv = 1.0 / (double)BHW;
        double mid = sums[0] * inv;
        double loss = 0.0;
#pragma unroll
        for (int n = 0; n < 4; n++) {
            double sL  = sums[1 + 4 * n] * inv;
            double sLL = sums[2 + 4 * n] * inv;
            double sR  = sums[3 + 4 * n] * inv;
            double sRR = sums[4 + 4 * n] * inv;
            float s2f = 0.f;
#pragma unroll
            for (int i = 0; i < 9; i++) s2f = fmaf(P.lam[n][i], P.lam[n][i], s2f);
            double s2 = (double)s2f;
            double d2 = 3.0 * s2;
            loss -= fmin(sL - mid - s2, 0.0);
            loss -= fmin(sL - sLL + d2, 0.0);
            loss -= fmin(sR - mid - s2, 0.0);
            loss -= fmin(sR - sRR + d2, 0.0);
        }
        out[0] = (float)loss;
        out[1] = (float)mid;
    }
}

// ---------------------------------------------------------------------------
// Host: JAX Threefry (partitionable) for gen_lambda
// ---------------------------------------------------------------------------
static inline void threefry2x32(uint32_t k0, uint32_t k1,
                                uint32_t x0, uint32_t x1,
                                uint32_t* o0, uint32_t* o1)
{
    const uint32_t ks[3] = {k0, k1, k0 ^ k1 ^ 0x1BD11BDAu};
    uint32_t v0 = x0 + ks[0];
    uint32_t v1 = x1 + ks[1];
    static const int rot[2][4] = {{13, 15, 26, 6}, {17, 29, 16, 24}};
    for (int g = 0; g < 5; g++) {
        const int* r = rot[g & 1];
        for (int i = 0; i < 4; i++) {
            v0 += v1;
            v1 = (v1 << r[i]) | (v1 >> (32 - r[i]));
            v1 ^= v0;
        }
        v0 += ks[(g + 1) % 3];
        v1 += ks[(g + 2) % 3] + (uint32_t)(g + 1);
    }
    *o0 = v0;
    *o1 = v1;
}

static void compute_lambdas(LamParams* P)
{
    for (int n = 0; n < 4; n++) {
        uint32_t k0, k1;
        threefry2x32(0u, 42u, 0u, (uint32_t)n, &k0, &k1);
        for (int i = 0; i < 9; i++) {
            uint32_t o0, o1;
            threefry2x32(k0, k1, 0u, (uint32_t)i, &o0, &o1);
            uint32_t bits = o0 ^ o1;
            uint32_t fb = (bits >> 9) | 0x3f800000u;
            float u;
            __builtin_memcpy(&u, &fb, 4);
            u -= 1.0f;
            float lam = (u - 0.5f) / 6.0f;
            if (lam > 0.f && lam < 0.02f)  lam = 0.02f;
            if (lam < 0.f && lam > -0.02f) lam = -0.02f;
            P->lam[n][i] = lam;
        }
        P->lam[n][8] = 0.0f;
    }
}

// ---------------------------------------------------------------------------
// Entry point
// ---------------------------------------------------------------------------
extern "C" void kernel_launch(void* const* d_in, const int* in_sizes, int n_in,
                              void* d_out, int out_size)
{
    (void)in_sizes; (void)n_in; (void)out_size;
    const float* tfeat = (const float*)d_in[0];
    const float* ifeat = (const float*)d_in[1];
    const float* tw    = (const float*)d_in[2];
    const float* iw    = (const float*)d_in[3];
    const float* Hgt   = (const float*)d_in[4];
    float* out = (float*)d_out;

    LamParams P;
    compute_lambdas(&P);

    float* tfm = out + OUT_TFM_OFF;
    float* ifm = out + OUT_IFM_OFF;

    dim3 fblk(TSX, TSY / 2);              // 32 x 8 = 256 threads
    dim3 fgrd(W / TSX, H / TSY, 2 * B);   // 4 x 8 x 16 = 512 blocks
    fmap_kernel<<<fgrd, fblk>>>(tfeat, ifeat, tfm);

    dim3 sgrd(HW / 256, B, NEVAL);
    ssim_kernel<<<sgrd, 256>>>(tfm, ifm, tw, iw, Hgt, P);

    final_kernel<<<1, 512>>>(out, P);
}

// round 4
// speedup vs baseline: 1.6813x; 1.3394x over previous
#include <cuda_runtime.h>
#include <cstdint>

#define B 8
#define C 64
#define H 128
#define W 128
#define HW (H * W)            // 16384
#define BHW (B * HW)          // 131072
#define NEVAL 17

#define OUT_TFM_OFF 2
#define OUT_IFM_OFF (2 + BHW)

struct LamParams {
    float lam[4][9];
};

// per-(eval, batch*block) partials
__device__ double g_part[NEVAL][512];

// ---------------------------------------------------------------------------
// Kernel 1: calc_fmap, barrier-free (register + shuffle) version.
//   Thread -> vertical pixel pair (rows py, py+1); loads 4 rows per channel.
//   Block: 256 threads = 128 x-positions * 2 pairs (covers 4 pixel rows).
//   Grid: (H/4, 2*B) = (32, 16).
// ---------------------------------------------------------------------------
__global__ __launch_bounds__(256)
void fmap_kernel(const float* __restrict__ tfeat, const float* __restrict__ ifeat,
                 float* __restrict__ out)
{
    const int z = blockIdx.y;                    // 0..15
    const int b = z & 7;
    const float* xb = ((z < B) ? tfeat : ifeat) + (size_t)b * C * HW;
    float* ob = out + (size_t)z * HW;

    const int tid  = threadIdx.x;
    const int x    = tid & 127;
    const int pair = tid >> 7;                   // 0..1
    const int py   = blockIdx.x * 4 + pair * 2;  // top pixel row of pair
    const int lane = tid & 31;
    const int warp = tid >> 5;                   // 0..7

    int   o[4];
    bool  rowv[4];
#pragma unroll
    for (int j = 0; j < 4; j++) {
        int rg = py - 1 + j;
        rowv[j] = ((unsigned)rg < (unsigned)H);
        o[j] = rowv[j] ? rg * W + x : 0;
    }

    const bool isL = (lane == 0);
    const bool isR = (lane == 31);
    const bool eok = (isL && x > 0) || (isR && x < W - 1);
    const int  eoff = isR ? 1 : -1;

    float A0[9], A1[9], P[4], Q[4];
#pragma unroll
    for (int k = 0; k < 9; k++) { A0[k] = 0.f; A1[k] = 0.f; }
#pragma unroll
    for (int j = 0; j < 4; j++) { P[j] = 0.f; Q[j] = 0.f; }

    const float* base = xb;
    for (int c = 0; c < C; c++, base += HW) {
        float cv[4], lv[4], rv[4];
#pragma unroll
        for (int j = 0; j < 4; j++)
            cv[j] = rowv[j] ? __ldg(base + o[j]) : 0.f;

#pragma unroll
        for (int j = 0; j < 4; j++) {
            float e = (eok && rowv[j]) ? __ldg(base + o[j] + eoff) : 0.f;
            float ls = __shfl_up_sync(0xffffffffu, cv[j], 1);
            float rs = __shfl_down_sync(0xffffffffu, cv[j], 1);
            lv[j] = isL ? e : ls;
            rv[j] = isR ? e : rs;
        }

        float rs4[4];
#pragma unroll
        for (int j = 0; j < 4; j++)
            rs4[j] = lv[j] + cv[j] + rv[j];
        float s0 = rs4[0] + rs4[1] + rs4[2];
        float s1 = rs4[1] + rs4[2] + rs4[3];

#pragma unroll
        for (int i = 0; i < 3; i++) {
            A0[3 * i + 0] = fmaf(lv[i],     s0, A0[3 * i + 0]);
            A0[3 * i + 1] = fmaf(cv[i],     s0, A0[3 * i + 1]);
            A0[3 * i + 2] = fmaf(rv[i],     s0, A0[3 * i + 2]);
            A1[3 * i + 0] = fmaf(lv[i + 1], s1, A1[3 * i + 0]);
            A1[3 * i + 1] = fmaf(cv[i + 1], s1, A1[3 * i + 1]);
            A1[3 * i + 2] = fmaf(rv[i + 1], s1, A1[3 * i + 2]);
        }
#pragma unroll
        for (int j = 0; j < 4; j++) {
            P[j] += cv[j];
            Q[j] = fmaf(cv[j], cv[j], Q[j]);
        }
    }

    // cross-warp exchange of edge P/Q (one barrier total)
    __shared__ float exL[8][8];   // lane0's  {P0..3, Q0..3} per warp
    __shared__ float exR[8][8];   // lane31's {P0..3, Q0..3} per warp
    if (isL) {
#pragma unroll
        for (int j = 0; j < 4; j++) { exL[warp][j] = P[j]; exL[warp][4 + j] = Q[j]; }
    }
    if (isR) {
#pragma unroll
        for (int j = 0; j < 4; j++) { exR[warp][j] = P[j]; exR[warp][4 + j] = Q[j]; }
    }
    __syncthreads();

    float Pl[4], Pr[4], Ql[4], Qr[4];
#pragma unroll
    for (int j = 0; j < 4; j++) {
        Pl[j] = __shfl_up_sync(0xffffffffu, P[j], 1);
        Ql[j] = __shfl_up_sync(0xffffffffu, Q[j], 1);
        Pr[j] = __shfl_down_sync(0xffffffffu, P[j], 1);
        Qr[j] = __shfl_down_sync(0xffffffffu, Q[j], 1);
    }
    if (isL) {
#pragma unroll
        for (int j = 0; j < 4; j++) {
            Pl[j] = (x > 0) ? exR[warp - 1][j]     : 0.f;
            Ql[j] = (x > 0) ? exR[warp - 1][4 + j] : 0.f;
        }
    }
    if (isR) {
#pragma unroll
        for (int j = 0; j < 4; j++) {
            Pr[j] = (x < W - 1) ? exL[warp + 1][j]     : 0.f;
            Qr[j] = (x < W - 1) ? exL[warp + 1][4 + j] : 0.f;
        }
    }

    // finalize both pixels
#pragma unroll
    for (int p = 0; p < 2; p++) {
        const float* Ak = p ? A1 : A0;
        float S1[9], T2 = 0.f;
#pragma unroll
        for (int i = 0; i < 3; i++) {
            int r = p + i;
            S1[3 * i + 0] = Pl[r];
            S1[3 * i + 1] = P[r];
            S1[3 * i + 2] = Pr[r];
            T2 += Ql[r] + Q[r] + Qr[r];
        }
        float mu[9], M = 0.f, musq = 0.f;
#pragma unroll
        for (int k = 0; k < 9; k++) {
            mu[k] = S1[k] * (1.f / C);
            M += mu[k];
            musq = fmaf(mu[k], mu[k], musq);
        }
        float trace = T2 - (float)C * musq;

        float rmax = -3.4e38f, rmin = 3.4e38f;
#pragma unroll
        for (int k = 0; k < 9; k++) {
            float rsv = Ak[k] - (float)C * mu[k] * M;
            rmax = fmaxf(rmax, rsv);
            rmin = fminf(rmin, rsv);
        }
        ob[(py + p) * W + x] = (rmax + rmin) * 0.5f / trace;
    }
}

// ---------------------------------------------------------------------------
// Kernel 2: warp + ssim, fp32 block reduction, all 17 evals
// ---------------------------------------------------------------------------
__global__ __launch_bounds__(256)
void ssim_kernel(const float* __restrict__ tfm, const float* __restrict__ ifm,
                 const float* __restrict__ tw,  const float* __restrict__ iw,
                 const float* __restrict__ Hgt, LamParams P)
{
    const int e   = blockIdx.z;
    const int b   = blockIdx.y;
    const int idx = blockIdx.x * 256 + threadIdx.x;

    float cf = 0.f;
    int n = 0;
    if (e > 0) {
        n = (e - 1) >> 2;
        int j = (e - 1) & 3;
        const float cs[4] = {1.f, 2.f, -1.f, -2.f};
        cf = cs[j];
    }

    float Hm[9];
#pragma unroll
    for (int i = 0; i < 9; i++) {
        float h = __ldg(&Hgt[b * 9 + i]);
        Hm[i] = h * (1.f + cf * P.lam[n][i]);
    }

    const int y = idx >> 7;
    const int x = idx & 127;
    const float fx = (float)x, fy = (float)y;

    float Z  = fmaf(Hm[6], fx, fmaf(Hm[7], fy, Hm[8]));
    float Xp = fmaf(Hm[0], fx, fmaf(Hm[1], fy, Hm[2]));
    float Yp = fmaf(Hm[3], fx, fmaf(Hm[4], fy, Hm[5]));
    float px = Xp / Z;
    float py = Yp / Z;

    float x0f = floorf(px), y0f = floorf(py);
    float x1f = x0f + 1.f,  y1f = y0f + 1.f;
    float wa = (x1f - px) * (y1f - py);
    float wb = (x1f - px) * (py - y0f);
    float wc = (px - x0f) * (y1f - py);
    float wd = (px - x0f) * (py - y0f);

    const float* fb  = ifm + (size_t)b * HW;
    const float* wbp = iw  + (size_t)b * HW;

    float wfm = 0.f, ww = 0.f;
#pragma unroll
    for (int t = 0; t < 4; t++) {
        float xi = (t & 2) ? x1f : x0f;
        float yi = (t & 1) ? y1f : y0f;
        float wt = (t == 0) ? wa : (t == 1) ? wb : (t == 2) ? wc : wd;
        float valid = (xi >= 0.f && xi <= (float)(W - 1) &&
                       yi >= 0.f && yi <= (float)(H - 1)) ? 1.f : 0.f;
        int xc = (int)fminf(fmaxf(xi, 0.f), (float)(W - 1));
        int yc = (int)fminf(fmaxf(yi, 0.f), (float)(H - 1));
        int off = yc * W + xc;
        wfm = fmaf(wt, __ldg(&fb[off])  * valid, wfm);
        ww  = fmaf(wt, __ldg(&wbp[off]) * valid, ww);
    }

    float t0  = __ldg(&tfm[(size_t)b * HW + idx]);
    float tw0 = __ldg(&tw[(size_t)b * HW + idx]);
    float d = t0 - wfm;
    float term = (tw0 * ww) * (d * d);

    const int lane = threadIdx.x & 31;
    const int warp = threadIdx.x >> 5;
#pragma unroll
    for (int o = 16; o > 0; o >>= 1)
        term += __shfl_down_sync(0xffffffffu, term, o);
    __shared__ float wsum[8];
    if (lane == 0) wsum[warp] = term;
    __syncthreads();
    if (warp == 0) {
        float s = (lane < 8) ? wsum[lane] : 0.f;
#pragma unroll
        for (int o = 4; o > 0; o >>= 1)
            s += __shfl_down_sync(0xffffffffu, s, o);
        if (lane == 0)
            g_part[e][b * 64 + blockIdx.x] = (double)s;
    }
}

// ---------------------------------------------------------------------------
// Kernel 3: final reduce + combine (single block, 512 threads)
// ---------------------------------------------------------------------------
__global__ __launch_bounds__(512)
void final_kernel(float* __restrict__ out, LamParams P)
{
    __shared__ double sums[NEVAL];
    __shared__ double wred[16];
    const int t = threadIdx.x;
    const int lane = t & 31, warp = t >> 5;

    for (int e = 0; e < NEVAL; e++) {
        double s = g_part[e][t];
#pragma unroll
        for (int o = 16; o > 0; o >>= 1)
            s += __shfl_down_sync(0xffffffffu, s, o);
        if (lane == 0) wred[warp] = s;
        __syncthreads();
        if (warp == 0) {
            double v = (lane < 16) ? wred[lane] : 0.0;
#pragma unroll
            for (int o = 8; o > 0; o >>= 1)
                v += __shfl_down_sync(0xffffffffu, v, o);
            if (lane == 0) sums[e] = v;
        }
        __syncthreads();
    }

    if (t == 0) {
        const double inv = 1.0 / (double)BHW;
        double mid = sums[0] * inv;
        double loss = 0.0;
#pragma unroll
        for (int n = 0; n < 4; n++) {
            double sL  = sums[1 + 4 * n] * inv;
            double sLL = sums[2 + 4 * n] * inv;
            double sR  = sums[3 + 4 * n] * inv;
            double sRR = sums[4 + 4 * n] * inv;
            float s2f = 0.f;
#pragma unroll
            for (int i = 0; i < 9; i++) s2f = fmaf(P.lam[n][i], P.lam[n][i], s2f);
            double s2 = (double)s2f;
            double d2 = 3.0 * s2;
            loss -= fmin(sL - mid - s2, 0.0);
            loss -= fmin(sL - sLL + d2, 0.0);
            loss -= fmin(sR - mid - s2, 0.0);
            loss -= fmin(sR - sRR + d2, 0.0);
        }
        out[0] = (float)loss;
        out[1] = (float)mid;
    }
}

// ---------------------------------------------------------------------------
// Host: JAX Threefry (partitionable) for gen_lambda
// ---------------------------------------------------------------------------
static inline void threefry2x32(uint32_t k0, uint32_t k1,
                                uint32_t x0, uint32_t x1,
                                uint32_t* o0, uint32_t* o1)
{
    const uint32_t ks[3] = {k0, k1, k0 ^ k1 ^ 0x1BD11BDAu};
    uint32_t v0 = x0 + ks[0];
    uint32_t v1 = x1 + ks[1];
    static const int rot[2][4] = {{13, 15, 26, 6}, {17, 29, 16, 24}};
    for (int g = 0; g < 5; g++) {
        const int* r = rot[g & 1];
        for (int i = 0; i < 4; i++) {
            v0 += v1;
            v1 = (v1 << r[i]) | (v1 >> (32 - r[i]));
            v1 ^= v0;
        }
        v0 += ks[(g + 1) % 3];
        v1 += ks[(g + 2) % 3] + (uint32_t)(g + 1);
    }
    *o0 = v0;
    *o1 = v1;
}

static void compute_lambdas(LamParams* P)
{
    for (int n = 0; n < 4; n++) {
        uint32_t k0, k1;
        threefry2x32(0u, 42u, 0u, (uint32_t)n, &k0, &k1);
        for (int i = 0; i < 9; i++) {
            uint32_t o0, o1;
            threefry2x32(k0, k1, 0u, (uint32_t)i, &o0, &o1);
            uint32_t bits = o0 ^ o1;
            uint32_t fb = (bits >> 9) | 0x3f800000u;
            float u;
            __builtin_memcpy(&u, &fb, 4);
            u -= 1.0f;
            float lam = (u - 0.5f) / 6.0f;
            if (lam > 0.f && lam < 0.02f)  lam = 0.02f;
            if (lam < 0.f && lam > -0.02f) lam = -0.02f;
            P->lam[n][i] = lam;
        }
        P->lam[n][8] = 0.0f;
    }
}

// ---------------------------------------------------------------------------
// Entry point
// ---------------------------------------------------------------------------
extern "C" void kernel_launch(void* const* d_in, const int* in_sizes, int n_in,
                              void* d_out, int out_size)
{
    (void)in_sizes; (void)n_in; (void)out_size;
    const float* tfeat = (const float*)d_in[0];
    const float* ifeat = (const float*)d_in[1];
    const float* tw    = (const float*)d_in[2];
    const float* iw    = (const float*)d_in[3];
    const float* Hgt   = (const float*)d_in[4];
    float* out = (float*)d_out;

    LamParams P;
    compute_lambdas(&P);

    float* tfm = out + OUT_TFM_OFF;
    float* ifm = out + OUT_IFM_OFF;

    dim3 fgrd(H / 4, 2 * B);              // (32, 16) = 512 blocks of 256
    fmap_kernel<<<fgrd, 256>>>(tfeat, ifeat, tfm);

    dim3 sgrd(HW / 256, B, NEVAL);
    ssim_kernel<<<sgrd, 256>>>(tfm, ifm, tw, iw, Hgt, P);

    final_kernel<<<1, 512>>>(out, P);
}

// round 6
// speedup vs baseline: 2.0204x; 1.2017x over previous
#include <cuda_runtime.h>
#include <cstdint>

#define B 8
#define C 64
#define H 128
#define W 128
#define HW (H * W)            // 16384
#define BHW (B * HW)          // 131072
#define NEVAL 17

#define OUT_TFM_OFF 2
#define OUT_IFM_OFF (2 + BHW)

struct LamParams {
    float lam[4][9];
};

// per-(eval, batch*block) partials: 17 x (8*64)
__device__ double g_part[NEVAL][512];

// ---------------------------------------------------------------------------
// Kernel 1: calc_fmap v3 — warp spans a full image row.
//   Lane loads float4 (x = 4*lane .. 4*lane+3) from rows y-1, y, y+1.
//   Horizontal halo: float4 components + 2 shuffles per row. No smem, no bar.
//   Block = 128 thr (4 warps = 4 rows). Grid (H/4, 2*B) = (32, 16).
//   NOTE: output base (d_out+2) is NOT 16B-aligned -> scalar stores only.
// ---------------------------------------------------------------------------
__global__ __launch_bounds__(128)
void fmap_kernel(const float* __restrict__ tfeat, const float* __restrict__ ifeat,
                 float* __restrict__ out)
{
    const int z = blockIdx.y;                 // 0..15
    const int b = z & 7;
    const float* xb = ((z < B) ? tfeat : ifeat) + (size_t)b * C * HW;
    float* ob = out + (size_t)z * HW;

    const int warp = threadIdx.x >> 5;        // 0..3
    const int lane = threadIdx.x & 31;
    const int y    = blockIdx.x * 4 + warp;   // output row
    const int x0   = lane * 4;

    const bool r0ok = (y > 0);
    const bool r2ok = (y < H - 1);
    const float* p0 = xb + (size_t)(y - 1) * W + x0;
    const float* p1 = xb + (size_t)y * W + x0;
    const float* p2 = xb + (size_t)(y + 1) * W + x0;

    float A[4][9];
    float P[3][4], Q[3][4];
#pragma unroll
    for (int i = 0; i < 4; i++)
#pragma unroll
        for (int k = 0; k < 9; k++) A[i][k] = 0.f;
#pragma unroll
    for (int r = 0; r < 3; r++)
#pragma unroll
        for (int i = 0; i < 4; i++) { P[r][i] = 0.f; Q[r][i] = 0.f; }

    for (int c = 0; c < C; c++) {
        float4 v[3];
        v[0] = r0ok ? __ldg((const float4*)(p0)) : make_float4(0.f, 0.f, 0.f, 0.f);
        v[1] = __ldg((const float4*)(p1));
        v[2] = r2ok ? __ldg((const float4*)(p2)) : make_float4(0.f, 0.f, 0.f, 0.f);
        p0 += HW; p1 += HW; p2 += HW;

        float e[3][6];
        float rowsum[3][4];
#pragma unroll
        for (int r = 0; r < 3; r++) {
            float L = __shfl_up_sync(0xffffffffu, v[r].w, 1);
            float R = __shfl_down_sync(0xffffffffu, v[r].x, 1);
            if (lane == 0)  L = 0.f;
            if (lane == 31) R = 0.f;
            e[r][0] = L; e[r][1] = v[r].x; e[r][2] = v[r].y;
            e[r][3] = v[r].z; e[r][4] = v[r].w; e[r][5] = R;
            float t01 = e[r][0] + e[r][1];
            float t23 = e[r][2] + e[r][3];
            float t45 = e[r][4] + e[r][5];
            rowsum[r][0] = t01 + e[r][2];
            rowsum[r][1] = e[r][1] + t23;
            rowsum[r][2] = t23 + e[r][4];
            rowsum[r][3] = e[r][3] + t45;
            P[r][0] += v[r].x; P[r][1] += v[r].y; P[r][2] += v[r].z; P[r][3] += v[r].w;
            Q[r][0] = fmaf(v[r].x, v[r].x, Q[r][0]);
            Q[r][1] = fmaf(v[r].y, v[r].y, Q[r][1]);
            Q[r][2] = fmaf(v[r].z, v[r].z, Q[r][2]);
            Q[r][3] = fmaf(v[r].w, v[r].w, Q[r][3]);
        }

        float s[4];
#pragma unroll
        for (int i = 0; i < 4; i++)
            s[i] = rowsum[0][i] + rowsum[1][i] + rowsum[2][i];

#pragma unroll
        for (int i = 0; i < 4; i++)
#pragma unroll
            for (int r = 0; r < 3; r++)
#pragma unroll
                for (int d = 0; d < 3; d++)
                    A[i][r * 3 + d] = fmaf(e[r][i + d], s[i], A[i][r * 3 + d]);
    }

    // one-time halo exchange of P/Q columns x0-1 and x0+4
    float PL[3], PR[3], QL[3], QR[3];
#pragma unroll
    for (int r = 0; r < 3; r++) {
        PL[r] = __shfl_up_sync(0xffffffffu, P[r][3], 1);
        QL[r] = __shfl_up_sync(0xffffffffu, Q[r][3], 1);
        PR[r] = __shfl_down_sync(0xffffffffu, P[r][0], 1);
        QR[r] = __shfl_down_sync(0xffffffffu, Q[r][0], 1);
        if (lane == 0)  { PL[r] = 0.f; QL[r] = 0.f; }
        if (lane == 31) { PR[r] = 0.f; QR[r] = 0.f; }
    }

    float res[4];
#pragma unroll
    for (int i = 0; i < 4; i++) {
        float S1[9], T2 = 0.f;
#pragma unroll
        for (int r = 0; r < 3; r++)
#pragma unroll
            for (int d = 0; d < 3; d++) {
                int col = i - 1 + d;
                float pv = (col < 0) ? PL[r] : (col > 3) ? PR[r] : P[r][col];
                float qv = (col < 0) ? QL[r] : (col > 3) ? QR[r] : Q[r][col];
                S1[r * 3 + d] = pv;
                T2 += qv;
            }
        float mu[9], M = 0.f, musq = 0.f;
#pragma unroll
        for (int k = 0; k < 9; k++) {
            mu[k] = S1[k] * (1.f / C);
            M += mu[k];
            musq = fmaf(mu[k], mu[k], musq);
        }
        float trace = T2 - (float)C * musq;

        float rmax = -3.4e38f, rmin = 3.4e38f;
#pragma unroll
        for (int k = 0; k < 9; k++) {
            float rsv = A[i][k] - (float)C * mu[k] * M;
            rmax = fmaxf(rmax, rsv);
            rmin = fminf(rmin, rsv);
        }
        res[i] = (rmax + rmin) * 0.5f / trace;
    }
    // scalar stores: output base is only 8B-aligned (d_out + 2 floats)
    float* op = ob + (size_t)y * W + x0;
    op[0] = res[0];
    op[1] = res[1];
    op[2] = res[2];
    op[3] = res[3];
}

// ---------------------------------------------------------------------------
// Kernel 2: warp + ssim, all 17 evals per thread (high MLP), fp32 reduce.
//   Grid (HW/256 = 64, B = 8), block 256.
// ---------------------------------------------------------------------------
__global__ __launch_bounds__(256)
void ssim_kernel(const float* __restrict__ tfm, const float* __restrict__ ifm,
                 const float* __restrict__ tw,  const float* __restrict__ iw,
                 const float* __restrict__ Hgt, LamParams P)
{
    const int b   = blockIdx.y;
    const int idx = blockIdx.x * 256 + threadIdx.x;

    float Hg[9];
#pragma unroll
    for (int i = 0; i < 9; i++)
        Hg[i] = __ldg(&Hgt[b * 9 + i]);

    const int y = idx >> 7;
    const int x = idx & 127;
    const float fx = (float)x, fy = (float)y;

    const float* fb  = ifm + (size_t)b * HW;
    const float* wbp = iw  + (size_t)b * HW;
    const float t0   = __ldg(&tfm[(size_t)b * HW + idx]);
    const float tw0  = __ldg(&tw[(size_t)b * HW + idx]);

    float acc[NEVAL];

#pragma unroll
    for (int e = 0; e < NEVAL; e++) {
        float cf = 0.f;
        int n = 0;
        if (e > 0) {
            n = (e - 1) >> 2;
            const int j = (e - 1) & 3;
            cf = (j == 0) ? 1.f : (j == 1) ? 2.f : (j == 2) ? -1.f : -2.f;
        }
        float Hm[9];
#pragma unroll
        for (int i = 0; i < 9; i++)
            Hm[i] = Hg[i] * (1.f + cf * P.lam[n][i]);

        float Z  = fmaf(Hm[6], fx, fmaf(Hm[7], fy, Hm[8]));
        float Xp = fmaf(Hm[0], fx, fmaf(Hm[1], fy, Hm[2]));
        float Yp = fmaf(Hm[3], fx, fmaf(Hm[4], fy, Hm[5]));
        float px = Xp / Z;
        float py = Yp / Z;

        float x0f = floorf(px), y0f = floorf(py);
        float x1f = x0f + 1.f,  y1f = y0f + 1.f;
        float wa = (x1f - px) * (y1f - py);
        float wb = (x1f - px) * (py - y0f);
        float wc = (px - x0f) * (y1f - py);
        float wd = (px - x0f) * (py - y0f);

        float wfm = 0.f, ww = 0.f;
#pragma unroll
        for (int t = 0; t < 4; t++) {
            float xi = (t & 2) ? x1f : x0f;
            float yi = (t & 1) ? y1f : y0f;
            float wt = (t == 0) ? wa : (t == 1) ? wb : (t == 2) ? wc : wd;
            float valid = (xi >= 0.f && xi <= (float)(W - 1) &&
                           yi >= 0.f && yi <= (float)(H - 1)) ? 1.f : 0.f;
            int xc = (int)fminf(fmaxf(xi, 0.f), (float)(W - 1));
            int yc = (int)fminf(fmaxf(yi, 0.f), (float)(H - 1));
            int off = yc * W + xc;
            wfm = fmaf(wt, __ldg(&fb[off])  * valid, wfm);
            ww  = fmaf(wt, __ldg(&wbp[off]) * valid, ww);
        }
        float d = t0 - wfm;
        acc[e] = (tw0 * ww) * (d * d);
    }

    // reduce all 17 sums
    const int lane = threadIdx.x & 31;
    const int warp = threadIdx.x >> 5;
    __shared__ float wsum[8][NEVAL];
#pragma unroll
    for (int e = 0; e < NEVAL; e++) {
        float v = acc[e];
#pragma unroll
        for (int o = 16; o > 0; o >>= 1)
            v += __shfl_down_sync(0xffffffffu, v, o);
        if (lane == 0) wsum[warp][e] = v;
    }
    __syncthreads();
    if (threadIdx.x < NEVAL) {
        const int e = threadIdx.x;
        float s = 0.f;
#pragma unroll
        for (int w = 0; w < 8; w++) s += wsum[w][e];
        g_part[e][b * 64 + blockIdx.x] = (double)s;
    }
}

// ---------------------------------------------------------------------------
// Kernel 3: final reduce + combine (single block, 512 threads)
// ---------------------------------------------------------------------------
__global__ __launch_bounds__(512)
void final_kernel(float* __restrict__ out, LamParams P)
{
    __shared__ double sums[NEVAL];
    __shared__ double wred[16];
    const int t = threadIdx.x;
    const int lane = t & 31, warp = t >> 5;

    for (int e = 0; e < NEVAL; e++) {
        double s = g_part[e][t];
#pragma unroll
        for (int o = 16; o > 0; o >>= 1)
            s += __shfl_down_sync(0xffffffffu, s, o);
        if (lane == 0) wred[warp] = s;
        __syncthreads();
        if (warp == 0) {
            double v = (lane < 16) ? wred[lane] : 0.0;
#pragma unroll
            for (int o = 8; o > 0; o >>= 1)
                v += __shfl_down_sync(0xffffffffu, v, o);
            if (lane == 0) sums[e] = v;
        }
        __syncthreads();
    }

    if (t == 0) {
        const double inv = 1.0 / (double)BHW;
        double mid = sums[0] * inv;
        double loss = 0.0;
#pragma unroll
        for (int n = 0; n < 4; n++) {
            double sL  = sums[1 + 4 * n] * inv;
            double sLL = sums[2 + 4 * n] * inv;
            double sR  = sums[3 + 4 * n] * inv;
            double sRR = sums[4 + 4 * n] * inv;
            float s2f = 0.f;
#pragma unroll
            for (int i = 0; i < 9; i++) s2f = fmaf(P.lam[n][i], P.lam[n][i], s2f);
            double s2 = (double)s2f;
            double d2 = 3.0 * s2;
            loss -= fmin(sL - mid - s2, 0.0);
            loss -= fmin(sL - sLL + d2, 0.0);
            loss -= fmin(sR - mid - s2, 0.0);
            loss -= fmin(sR - sRR + d2, 0.0);
        }
        out[0] = (float)loss;
        out[1] = (float)mid;
    }
}

// ---------------------------------------------------------------------------
// Host: JAX Threefry (partitionable) for gen_lambda
// ---------------------------------------------------------------------------
static inline void threefry2x32(uint32_t k0, uint32_t k1,
                                uint32_t x0, uint32_t x1,
                                uint32_t* o0, uint32_t* o1)
{
    const uint32_t ks[3] = {k0, k1, k0 ^ k1 ^ 0x1BD11BDAu};
    uint32_t v0 = x0 + ks[0];
    uint32_t v1 = x1 + ks[1];
    static const int rot[2][4] = {{13, 15, 26, 6}, {17, 29, 16, 24}};
    for (int g = 0; g < 5; g++) {
        const int* r = rot[g & 1];
        for (int i = 0; i < 4; i++) {
            v0 += v1;
            v1 = (v1 << r[i]) | (v1 >> (32 - r[i]));
            v1 ^= v0;
        }
        v0 += ks[(g + 1) % 3];
        v1 += ks[(g + 2) % 3] + (uint32_t)(g + 1);
    }
    *o0 = v0;
    *o1 = v1;
}

static void compute_lambdas(LamParams* P)
{
    for (int n = 0; n < 4; n++) {
        uint32_t k0, k1;
        threefry2x32(0u, 42u, 0u, (uint32_t)n, &k0, &k1);
        for (int i = 0; i < 9; i++) {
            uint32_t o0, o1;
            threefry2x32(k0, k1, 0u, (uint32_t)i, &o0, &o1);
            uint32_t bits = o0 ^ o1;
            uint32_t fb = (bits >> 9) | 0x3f800000u;
            float u;
            __builtin_memcpy(&u, &fb, 4);
            u -= 1.0f;
            float lam = (u - 0.5f) / 6.0f;
            if (lam > 0.f && lam < 0.02f)  lam = 0.02f;
            if (lam < 0.f && lam > -0.02f) lam = -0.02f;
            P->lam[n][i] = lam;
        }
        P->lam[n][8] = 0.0f;
    }
}

// ---------------------------------------------------------------------------
// Entry point
// ---------------------------------------------------------------------------
extern "C" void kernel_launch(void* const* d_in, const int* in_sizes, int n_in,
                              void* d_out, int out_size)
{
    (void)in_sizes; (void)n_in; (void)out_size;
    const float* tfeat = (const float*)d_in[0];
    const float* ifeat = (const float*)d_in[1];
    const float* tw    = (const float*)d_in[2];
    const float* iw    = (const float*)d_in[3];
    const float* Hgt   = (const float*)d_in[4];
    float* out = (float*)d_out;

    LamParams P;
    compute_lambdas(&P);

    float* tfm = out + OUT_TFM_OFF;
    float* ifm = out + OUT_IFM_OFF;

    dim3 fgrd(H / 4, 2 * B);              // (32, 16) = 512 blocks of 128
    fmap_kernel<<<fgrd, 128>>>(tfeat, ifeat, tfm);

    dim3 sgrd(HW / 256, B);               // (64, 8) = 512 blocks of 256
    ssim_kernel<<<sgrd, 256>>>(tfm, ifm, tw, iw, Hgt, P);

    final_kernel<<<1, 512>>>(out, P);
}